// round 14
// baseline (speedup 1.0000x reference)
#include <cuda_runtime.h>
#include <cuda_fp16.h>
#include <cuda_bf16.h>
#include <cstdint>
#include <math.h>

#define MAXN 100000
#define MAXE 1600000
#define FD   128      // IN == HID == 128
#define OUTC 64

// ---------------- scratch (device globals; no allocation allowed) ----------
// Invariant: g_cnt / g_status / g_ticket are zero before and after every run.
__device__ __half g_bufU[MAXN * FD];  // U (gemm1 out), later V (fp16)
__device__ float  g_bufA[MAXN * FD];  // h (agg1 out, fp32)
__device__ int    g_cnt[MAXN];
__device__ int    g_rowptr[MAXN + 1];
__device__ int    g_cursor[MAXN];
__device__ __align__(16) int2 g_csrw[MAXE];  // (src byte-offset, dinv[src] bits)
__device__ float  g_dinv[MAXN];
__device__ unsigned long long g_status[512];
__device__ unsigned int g_ticket;

// ---------------- degree count (4 edges/thread) -----------------------------
__global__ void k_count(const int* __restrict__ ei, int e) {
    int i4 = (blockIdx.x * blockDim.x + threadIdx.x) * 4;
    if (i4 + 4 <= e) {
        int d0 = __ldg(&ei[e + i4]);
        int d1 = __ldg(&ei[e + i4 + 1]);
        int d2 = __ldg(&ei[e + i4 + 2]);
        int d3 = __ldg(&ei[e + i4 + 3]);
        atomicAdd(&g_cnt[d0], 1);
        atomicAdd(&g_cnt[d1], 1);
        atomicAdd(&g_cnt[d2], 1);
        atomicAdd(&g_cnt[d3], 1);
    } else {
        for (int i = i4; i < e; i++)
            atomicAdd(&g_cnt[__ldg(&ei[e + i])], 1);
    }
}

// ---------------- single-pass scan (decoupled lookback) ---------------------
__global__ void k_scan_lb(int n) {
    __shared__ int s_vbid;
    __shared__ int s_excl;
    __shared__ int wsum[8], woff[8];
    int tid = threadIdx.x, lane = tid & 31, w = tid >> 5;

    if (tid == 0) s_vbid = (int)atomicAdd(&g_ticket, 1u);
    __syncthreads();
    int vbid = s_vbid;
    int i = vbid * 256 + tid;

    int val = 0;
    if (i < n) { val = g_cnt[i]; g_cnt[i] = 0; }   // consume + self-clean
    int x = val;
#pragma unroll
    for (int o = 1; o < 32; o <<= 1) {
        int t = __shfl_up_sync(0xFFFFFFFFu, x, o);
        if (lane >= o) x += t;
    }
    if (lane == 31) wsum[w] = x;
    __syncthreads();
    if (tid < 8) {
        int ws = wsum[tid];
        int y = ws;
#pragma unroll
        for (int o = 1; o < 8; o <<= 1) {
            int t = __shfl_up_sync(0xFFu, y, o);
            if (tid >= o) y += t;
        }
        woff[tid] = y - ws;
        if (tid == 7) wsum[0] = y;
    }
    __syncthreads();
    int incl = woff[w] + x;
    int agg = wsum[0];

    if (tid == 0) {
        if (vbid == 0) {
            atomicExch(&g_status[0], (2ULL << 32) | (unsigned long long)(unsigned)agg);
            s_excl = 0;
        } else {
            atomicExch(&g_status[vbid], (1ULL << 32) | (unsigned long long)(unsigned)agg);
            int sum = 0;
            int p = vbid - 1;
            while (true) {
                unsigned long long s = atomicAdd(&g_status[p], 0ULL);
                unsigned flag = (unsigned)(s >> 32);
                if (flag == 0u) continue;
                sum += (int)(unsigned)s;
                if (flag == 2u) break;
                p--;
            }
            atomicExch(&g_status[vbid], (2ULL << 32) | (unsigned long long)(unsigned)(sum + agg));
            s_excl = sum;
        }
    }
    __syncthreads();
    int base = s_excl;

    if (i < n) {
        int excl = base + incl - val;
        g_rowptr[i] = excl;
        g_cursor[i] = excl;
        g_dinv[i] = rsqrtf((float)val + 1.0f);
        if (i == n - 1) g_rowptr[n] = base + incl;
    }
}

// ---------------- CSR fill (4 edges/thread) + lookback-state cleanup --------
// stores (src*256, dinv bits)
__global__ void k_fill(const int* __restrict__ ei, int e) {
    int gid = blockIdx.x * blockDim.x + threadIdx.x;
    if (gid < 512) g_status[gid] = 0ULL;
    if (gid == 0) g_ticket = 0u;

    int i4 = gid * 4;
    if (i4 + 4 <= e) {
        int4 ss = __ldg((const int4*)&ei[i4]);
        int d0 = __ldg(&ei[e + i4]);
        int d1 = __ldg(&ei[e + i4 + 1]);
        int d2 = __ldg(&ei[e + i4 + 2]);
        int d3 = __ldg(&ei[e + i4 + 3]);
        float w0 = __ldg(&g_dinv[ss.x]);
        float w1 = __ldg(&g_dinv[ss.y]);
        float w2 = __ldg(&g_dinv[ss.z]);
        float w3 = __ldg(&g_dinv[ss.w]);
        int p0 = atomicAdd(&g_cursor[d0], 1);
        int p1 = atomicAdd(&g_cursor[d1], 1);
        int p2 = atomicAdd(&g_cursor[d2], 1);
        int p3 = atomicAdd(&g_cursor[d3], 1);
        g_csrw[p0] = make_int2(ss.x << 8, __float_as_int(w0));
        g_csrw[p1] = make_int2(ss.y << 8, __float_as_int(w1));
        g_csrw[p2] = make_int2(ss.z << 8, __float_as_int(w2));
        g_csrw[p3] = make_int2(ss.w << 8, __float_as_int(w3));
    } else {
        for (int i = i4; i < e; i++) {
            int s = __ldg(&ei[i]);
            int d = __ldg(&ei[e + i]);
            float w = __ldg(&g_dinv[s]);
            int p = atomicAdd(&g_cursor[d], 1);
            g_csrw[p] = make_int2(s << 8, __float_as_int(w));
        }
    }
}

// ---------------- fp16 gather core (byte-offset CSR, 4-row MLP) -------------
__device__ __forceinline__ float4 agg_gather(const __half* __restrict__ X,
                                             int node, int lane, float di) {
    const char* Xc = (const char*)X;     // 256B per row
    int loff = lane * 8;
    uint2 sr = __ldg((const uint2*)(Xc + (size_t)node * 256 + loff));
    float2 f01 = __half22float2(*(__half2*)&sr.x);
    float2 f23 = __half22float2(*(__half2*)&sr.y);
    float4 acc = make_float4(di * f01.x, di * f01.y, di * f23.x, di * f23.y);

    int s0 = __ldg(&g_rowptr[node]), s1 = __ldg(&g_rowptr[node + 1]);

#define AG_FMA(rr, ww) {                                                       \
        float2 a = __half22float2(*(__half2*)&(rr).x);                         \
        float2 b = __half22float2(*(__half2*)&(rr).y);                         \
        acc.x += (ww) * a.x; acc.y += (ww) * a.y;                              \
        acc.z += (ww) * b.x; acc.w += (ww) * b.y; }
#define AG_ROW(off) __ldg((const uint2*)(Xc + (uint32_t)(off) + loff))

    int e = s0;
    if (e < s1 && (e & 1)) {                  // peel to even for int4 loads
        int2 p = __ldg(&g_csrw[e]);
        uint2 r = AG_ROW(p.x);
        AG_FMA(r, __int_as_float(p.y));
        e++;
    }
    for (; e + 4 <= s1; e += 4) {
        int4 q0 = __ldg((const int4*)&g_csrw[e]);
        int4 q1 = __ldg((const int4*)&g_csrw[e + 2]);
        uint2 r0 = AG_ROW(q0.x);
        uint2 r1 = AG_ROW(q0.z);
        uint2 r2 = AG_ROW(q1.x);
        uint2 r3 = AG_ROW(q1.z);
        AG_FMA(r0, __int_as_float(q0.y));
        AG_FMA(r1, __int_as_float(q0.w));
        AG_FMA(r2, __int_as_float(q1.y));
        AG_FMA(r3, __int_as_float(q1.w));
    }
    if (e + 2 <= s1) {
        int4 q0 = __ldg((const int4*)&g_csrw[e]);
        uint2 r0 = AG_ROW(q0.x);
        uint2 r1 = AG_ROW(q0.z);
        AG_FMA(r0, __int_as_float(q0.y));
        AG_FMA(r1, __int_as_float(q0.w));
        e += 2;
    }
    if (e < s1) {
        int2 p = __ldg(&g_csrw[e]);
        uint2 r = AG_ROW(p.x);
        AG_FMA(r, __int_as_float(p.y));
    }
#undef AG_ROW
#undef AG_FMA
    acc.x *= di; acc.y *= di; acc.z *= di; acc.w *= di;
    return acc;
}

// ---- agg1: h = Agg(U) + b1  (fp16 in, fp32 out); 128-thread blocks ---------
__global__ void __launch_bounds__(128)
k_agg_bias(const __half* __restrict__ X, float* __restrict__ Y,
           const float* __restrict__ bias, int n) {
    int gw = (blockIdx.x * blockDim.x + threadIdx.x) >> 5;
    int lane = threadIdx.x & 31;
    if (gw >= n) return;
    float di = __ldg(&g_dinv[gw]);
    float4 acc = agg_gather(X, gw, lane, di);
    float4 b = __ldg((const float4*)&bias[lane * 4]);
    acc.x += b.x; acc.y += b.y; acc.z += b.z; acc.w += b.w;
    ((float4*)Y)[(size_t)gw * 32 + lane] = acc;
}

// ---- agg2: [mu|ls] = Agg(V)+bias; out = mu + init*exp(ls) ------------------
__global__ void __launch_bounds__(128)
k_agg_out(const __half* __restrict__ X,
          const float* __restrict__ bmu, const float* __restrict__ bls,
          const float* __restrict__ initd,
          float* __restrict__ out, int n) {
    int gw = (blockIdx.x * blockDim.x + threadIdx.x) >> 5;
    int lane = threadIdx.x & 31;
    if (gw >= n) return;
    float di = __ldg(&g_dinv[gw]);
    float4 v = agg_gather(X, gw, lane, di);
    float4 b = (lane < 16) ? __ldg((const float4*)&bmu[lane * 4])
                           : __ldg((const float4*)&bls[lane * 4 - 64]);
    v.x += b.x; v.y += b.y; v.z += b.z; v.w += b.w;
    float4 p;
    p.x = __shfl_xor_sync(0xFFFFFFFFu, v.x, 16);
    p.y = __shfl_xor_sync(0xFFFFFFFFu, v.y, 16);
    p.z = __shfl_xor_sync(0xFFFFFFFFu, v.z, 16);
    p.w = __shfl_xor_sync(0xFFFFFFFFu, v.w, 16);
    if (lane < 16) {
        float4 ini = __ldg((const float4*)&initd[(size_t)gw * 64 + lane * 4]);
        float4 o;
        o.x = v.x + ini.x * expf(p.x);
        o.y = v.y + ini.y * expf(p.y);
        o.z = v.z + ini.z * expf(p.z);
        o.w = v.w + ini.w * expf(p.w);
        *(float4*)&out[(size_t)gw * 64 + lane * 4] = o;
    }
}

// ================= shared GEMM pieces =======================================
#define KS_B 136
#define SOFF_BH 0
#define SOFF_BL (128 * KS_B * 2)
#define SMEM_MMA (SOFF_BL + 128 * KS_B * 2)

__device__ __forceinline__ void split2(float a, float b, uint32_t& hi, uint32_t& lo) {
    __nv_bfloat16 ah = __float2bfloat16(a), bh = __float2bfloat16(b);
    float ar = a - __bfloat162float(ah);
    float br = b - __bfloat162float(bh);
    __nv_bfloat16 al = __float2bfloat16(ar), bl = __float2bfloat16(br);
    __nv_bfloat162 h; h.x = ah; h.y = bh;
    __nv_bfloat162 l; l.x = al; l.y = bl;
    hi = *(uint32_t*)&h;
    lo = *(uint32_t*)&l;
}

__device__ __forceinline__ uint32_t smem_u32(const void* p) {
    uint32_t a;
    asm("{ .reg .u64 t; cvta.to.shared.u64 t, %1; cvt.u32.u64 %0, t; }" : "=r"(a) : "l"(p));
    return a;
}

__device__ __forceinline__ void mma_bf16(float& c0, float& c1, float& c2, float& c3,
                                         uint32_t a0, uint32_t a1, uint32_t a2, uint32_t a3,
                                         uint32_t b0, uint32_t b1) {
    asm volatile(
        "mma.sync.aligned.m16n8k16.row.col.f32.bf16.bf16.f32 "
        "{%0,%1,%2,%3}, {%4,%5,%6,%7}, {%8,%9}, {%0,%1,%2,%3};"
        : "+f"(c0), "+f"(c1), "+f"(c2), "+f"(c3)
        : "r"(a0), "r"(a1), "r"(a2), "r"(a3), "r"(b0), "r"(b1));
}

__device__ __forceinline__ void ldsm_x2(uint32_t& r0, uint32_t& r1, uint32_t addr) {
    asm volatile("ldmatrix.sync.aligned.m8n8.x2.shared.b16 {%0, %1}, [%2];"
        : "=r"(r0), "=r"(r1) : "r"(addr));
}

// ---- generic split-bf16 3-pass GEMM: fp32 A, fp16 out ----------------------
__global__ void __launch_bounds__(256)
k_mma_gemm(const float* __restrict__ A,
           const float* __restrict__ Wa, int Na,
           const float* __restrict__ Wb,
           __half* __restrict__ C, int n) {
    extern __shared__ char smem[];
    uint16_t* BH = (uint16_t*)(smem + SOFF_BH);
    uint16_t* BL = (uint16_t*)(smem + SOFF_BL);
    int tid = threadIdx.x;
    int wid = tid >> 5, lane = tid & 31;
    int row0 = blockIdx.x * 128;
    int Nb = 128 - Na;

    {
        int col = tid >> 1;
        int kbeg = (tid & 1) * 64;
        const float* Wcol = (col < Na) ? (Wa + col) : (Wb + (col - Na));
        int stride = (col < Na) ? Na : Nb;
#pragma unroll 8
        for (int k = kbeg; k < kbeg + 64; k++) {
            float w = __ldg(&Wcol[k * stride]);
            __nv_bfloat16 wh = __float2bfloat16(w);
            float wr = w - __bfloat162float(wh);
            __nv_bfloat16 wl = __float2bfloat16(wr);
            BH[col * KS_B + k] = *(uint16_t*)&wh;
            BL[col * KS_B + k] = *(uint16_t*)&wl;
        }
    }

    int rbase = row0 + wid * 16;
    int r0 = rbase + (lane >> 2);
    int r1 = r0 + 8;
    int r0c = (r0 < n) ? r0 : 0;
    int r1c = (r1 < n) ? r1 : 0;
    const float* A0 = A + (size_t)r0c * 128;
    const float* A1 = A + (size_t)r1c * 128;
    int cc = (lane & 3) * 2;

    uint32_t aH[8][4], aL[8][4];
#pragma unroll
    for (int ks = 0; ks < 8; ks++) {
        int k0 = ks * 16;
        float2 v00 = __ldg((const float2*)&A0[k0 + cc]);
        float2 v10 = __ldg((const float2*)&A1[k0 + cc]);
        float2 v02 = __ldg((const float2*)&A0[k0 + cc + 8]);
        float2 v12 = __ldg((const float2*)&A1[k0 + cc + 8]);
        split2(v00.x, v00.y, aH[ks][0], aL[ks][0]);
        split2(v10.x, v10.y, aH[ks][1], aL[ks][1]);
        split2(v02.x, v02.y, aH[ks][2], aL[ks][2]);
        split2(v12.x, v12.y, aH[ks][3], aL[ks][3]);
    }

    __syncthreads();

    uint32_t bh_base = smem_u32(BH);
    uint32_t bl_base = smem_u32(BL);
    uint32_t lrow = (uint32_t)(lane & 7);
    uint32_t khalf = ((uint32_t)(lane >> 3) & 1) * 8;

    bool w0 = (r0 < n), w1 = (r1 < n);
    __half* C0 = C + (size_t)r0c * 128;
    __half* C1 = C + (size_t)r1c * 128;

#pragma unroll 2
    for (int nb = 0; nb < 16; nb++) {
        int n0 = nb * 8;
        uint32_t off = ((n0 + lrow) * KS_B + khalf) * 2;
        uint32_t adH = bh_base + off;
        uint32_t adL = bl_base + off;
        float c0 = 0.f, c1 = 0.f, c2 = 0.f, c3 = 0.f;
#pragma unroll
        for (int ks = 0; ks < 8; ks++) {
            uint32_t bh0, bh1, bl0, bl1;
            ldsm_x2(bh0, bh1, adH + ks * 32);
            ldsm_x2(bl0, bl1, adL + ks * 32);
            mma_bf16(c0, c1, c2, c3, aH[ks][0], aH[ks][1], aH[ks][2], aH[ks][3], bh0, bh1);
            mma_bf16(c0, c1, c2, c3, aH[ks][0], aH[ks][1], aH[ks][2], aH[ks][3], bl0, bl1);
            mma_bf16(c0, c1, c2, c3, aL[ks][0], aL[ks][1], aL[ks][2], aL[ks][3], bh0, bh1);
        }
        if (w0) *(__half2*)&C0[n0 + cc] = __floats2half2_rn(c0, c1);
        if (w1) *(__half2*)&C1[n0 + cc] = __floats2half2_rn(c2, c3);
    }
}

// ---------------- launch ----------------------------------------------------
// Graph-capture parallel fork: CSR build chain (count->scan->fill) runs on a
// non-blocking side stream concurrently with the layer-1 GEMM. Stream/event
// handles are host-side only (no device memory); kernel_launch is invoked only
// for correctness + one capture, so the tiny handle leak is bounded.
extern "C" void kernel_launch(void* const* d_in, const int* in_sizes, int n_in,
                              void* d_out, int out_size) {
    const float* x    = (const float*)d_in[0];
    const int*   ei   = (const int*)d_in[1];
    const float* initd= (const float*)d_in[2];
    const float* W1   = (const float*)d_in[3];
    const float* b1   = (const float*)d_in[4];
    const float* Wmu  = (const float*)d_in[5];
    const float* bmu  = (const float*)d_in[6];
    const float* Wls  = (const float*)d_in[7];
    const float* bls  = (const float*)d_in[8];
    float* out = (float*)d_out;

    int n = in_sizes[0] / FD;
    int e = in_sizes[1] / 2;

    void *pU = nullptr, *pA = nullptr;
    cudaGetSymbolAddress(&pU, g_bufU);
    cudaGetSymbolAddress(&pA, g_bufA);
    __half* bufU = (__half*)pU;
    float*  bufA = (float*)pA;

    cudaFuncSetAttribute(k_mma_gemm, cudaFuncAttributeMaxDynamicSharedMemorySize, SMEM_MMA);

    int agg_grid = (n + 3) / 4;            // 128-thread blocks, 4 warps each
    int gemm_grid = (n + 127) / 128;
    int scan_grid = (n + 255) / 256;
    int q_grid = ((e + 3) / 4 + 255) / 256;

    cudaStream_t s2 = nullptr;
    cudaEvent_t e0 = nullptr, e1 = nullptr;
    bool forked = (cudaStreamCreateWithFlags(&s2, cudaStreamNonBlocking) == cudaSuccess) &&
                  (cudaEventCreateWithFlags(&e0, cudaEventDisableTiming) == cudaSuccess) &&
                  (cudaEventCreateWithFlags(&e1, cudaEventDisableTiming) == cudaSuccess);

    if (forked) {
        cudaEventRecord(e0, 0);            // fork point on capturing stream
        cudaStreamWaitEvent(s2, e0, 0);
        // side stream: CSR build chain
        k_count<<<q_grid, 256, 0, s2>>>(ei, e);
        k_scan_lb<<<scan_grid, 256, 0, s2>>>(n);
        k_fill<<<q_grid, 256, 0, s2>>>(ei, e);
        cudaEventRecord(e1, s2);
        // main stream (parallel): U = x @ W1 (fp16)
        k_mma_gemm<<<gemm_grid, 256, SMEM_MMA>>>(x, W1, 128, W1, bufU, n);
        cudaStreamWaitEvent(0, e1, 0);     // join before agg1
    } else {
        // serial fallback
        k_count<<<q_grid, 256>>>(ei, e);
        k_scan_lb<<<scan_grid, 256>>>(n);
        k_fill<<<q_grid, 256>>>(ei, e);
        k_mma_gemm<<<gemm_grid, 256, SMEM_MMA>>>(x, W1, 128, W1, bufU, n);
    }

    // h = Agg(U) + b1 (fp32)
    k_agg_bias<<<agg_grid, 128>>>(bufU, bufA, b1, n);

    // layer 2: V = h @ [Wmu|Wls] (fp16); out = Agg(V)+bias, reparametrized
    k_mma_gemm<<<gemm_grid, 256, SMEM_MMA>>>(bufA, Wmu, 64, Wls, bufU, n);
    k_agg_out<<<agg_grid, 128>>>(bufU, bmu, bls, initd, out, n);
}

// round 15
// speedup vs baseline: 1.3572x; 1.3572x over previous
#include <cuda_runtime.h>
#include <cuda_fp16.h>
#include <cuda_bf16.h>
#include <cstdint>
#include <math.h>

#define MAXN 100000
#define MAXE 1600000
#define FD   128      // IN == HID == 128
#define OUTC 64

// ---------------- scratch (device globals; no allocation allowed) ----------
// Invariant: g_cnt / g_status / g_ticket are zero before and after every run.
__device__ __half g_bufU[MAXN * FD];  // U (gemm1 out), later V (fp16)
__device__ float  g_bufA[MAXN * FD];  // h (agg1 out, fp32)
__device__ int    g_cnt[MAXN];
__device__ int    g_rowptr[MAXN + 1];
__device__ int    g_cursor[MAXN];
__device__ __align__(16) int2 g_csrw[MAXE];  // (src byte-offset, dinv[src] bits)
__device__ float  g_dinv[MAXN];
__device__ unsigned long long g_status[512];
__device__ unsigned int g_ticket;

// ---------------- single-pass scan (decoupled lookback) ---------------------
__global__ void k_scan_lb(int n) {
    __shared__ int s_vbid;
    __shared__ int s_excl;
    __shared__ int wsum[8], woff[8];
    int tid = threadIdx.x, lane = tid & 31, w = tid >> 5;

    if (tid == 0) s_vbid = (int)atomicAdd(&g_ticket, 1u);
    __syncthreads();
    int vbid = s_vbid;
    int i = vbid * 256 + tid;

    int val = 0;
    if (i < n) { val = g_cnt[i]; g_cnt[i] = 0; }   // consume + self-clean
    int x = val;
#pragma unroll
    for (int o = 1; o < 32; o <<= 1) {
        int t = __shfl_up_sync(0xFFFFFFFFu, x, o);
        if (lane >= o) x += t;
    }
    if (lane == 31) wsum[w] = x;
    __syncthreads();
    if (tid < 8) {
        int ws = wsum[tid];
        int y = ws;
#pragma unroll
        for (int o = 1; o < 8; o <<= 1) {
            int t = __shfl_up_sync(0xFFu, y, o);
            if (tid >= o) y += t;
        }
        woff[tid] = y - ws;
        if (tid == 7) wsum[0] = y;
    }
    __syncthreads();
    int incl = woff[w] + x;
    int agg = wsum[0];

    if (tid == 0) {
        if (vbid == 0) {
            atomicExch(&g_status[0], (2ULL << 32) | (unsigned long long)(unsigned)agg);
            s_excl = 0;
        } else {
            atomicExch(&g_status[vbid], (1ULL << 32) | (unsigned long long)(unsigned)agg);
            int sum = 0;
            int p = vbid - 1;
            while (true) {
                unsigned long long s = atomicAdd(&g_status[p], 0ULL);
                unsigned flag = (unsigned)(s >> 32);
                if (flag == 0u) continue;
                sum += (int)(unsigned)s;
                if (flag == 2u) break;
                p--;
            }
            atomicExch(&g_status[vbid], (2ULL << 32) | (unsigned long long)(unsigned)(sum + agg));
            s_excl = sum;
        }
    }
    __syncthreads();
    int base = s_excl;

    if (i < n) {
        int excl = base + incl - val;
        g_rowptr[i] = excl;
        g_cursor[i] = excl;
        g_dinv[i] = rsqrtf((float)val + 1.0f);
        if (i == n - 1) g_rowptr[n] = base + incl;
    }
}

// ---------------- CSR fill (2 edges/thread) + lookback-state cleanup --------
// stores (src*256, dinv bits)
__global__ void k_fill(const int* __restrict__ ei, int e) {
    int gid = blockIdx.x * blockDim.x + threadIdx.x;
    if (gid < 512) g_status[gid] = 0ULL;
    if (gid == 0) g_ticket = 0u;

    int i2 = gid * 2;
    if (i2 + 1 < e) {
        int2 ss = __ldg((const int2*)&ei[i2]);
        int2 dd = __ldg((const int2*)&ei[e + i2]);
        float w0 = __ldg(&g_dinv[ss.x]);
        float w1 = __ldg(&g_dinv[ss.y]);
        int p0 = atomicAdd(&g_cursor[dd.x], 1);
        g_csrw[p0] = make_int2(ss.x << 8, __float_as_int(w0));
        int p1 = atomicAdd(&g_cursor[dd.y], 1);
        g_csrw[p1] = make_int2(ss.y << 8, __float_as_int(w1));
    } else if (i2 < e) {
        int s = __ldg(&ei[i2]);
        int d = __ldg(&ei[e + i2]);
        float w = __ldg(&g_dinv[s]);
        int p = atomicAdd(&g_cursor[d], 1);
        g_csrw[p] = make_int2(s << 8, __float_as_int(w));
    }
}

// ---------------- fp16 gather core (byte-offset CSR, 4-row MLP) -------------
__device__ __forceinline__ float4 agg_gather(const __half* __restrict__ X,
                                             int node, int lane, float di) {
    const char* Xc = (const char*)X;     // 256B per row
    int loff = lane * 8;
    uint2 sr = __ldg((const uint2*)(Xc + (size_t)node * 256 + loff));
    float2 f01 = __half22float2(*(__half2*)&sr.x);
    float2 f23 = __half22float2(*(__half2*)&sr.y);
    float4 acc = make_float4(di * f01.x, di * f01.y, di * f23.x, di * f23.y);

    int s0 = __ldg(&g_rowptr[node]), s1 = __ldg(&g_rowptr[node + 1]);

#define AG_FMA(rr, ww) {                                                       \
        float2 a = __half22float2(*(__half2*)&(rr).x);                         \
        float2 b = __half22float2(*(__half2*)&(rr).y);                         \
        acc.x += (ww) * a.x; acc.y += (ww) * a.y;                              \
        acc.z += (ww) * b.x; acc.w += (ww) * b.y; }
#define AG_ROW(off) __ldg((const uint2*)(Xc + (uint32_t)(off) + loff))

    int e = s0;
    if (e < s1 && (e & 1)) {                  // peel to even for int4 loads
        int2 p = __ldg(&g_csrw[e]);
        uint2 r = AG_ROW(p.x);
        AG_FMA(r, __int_as_float(p.y));
        e++;
    }
    for (; e + 4 <= s1; e += 4) {
        int4 q0 = __ldg((const int4*)&g_csrw[e]);
        int4 q1 = __ldg((const int4*)&g_csrw[e + 2]);
        uint2 r0 = AG_ROW(q0.x);
        uint2 r1 = AG_ROW(q0.z);
        uint2 r2 = AG_ROW(q1.x);
        uint2 r3 = AG_ROW(q1.z);
        AG_FMA(r0, __int_as_float(q0.y));
        AG_FMA(r1, __int_as_float(q0.w));
        AG_FMA(r2, __int_as_float(q1.y));
        AG_FMA(r3, __int_as_float(q1.w));
    }
    if (e + 2 <= s1) {
        int4 q0 = __ldg((const int4*)&g_csrw[e]);
        uint2 r0 = AG_ROW(q0.x);
        uint2 r1 = AG_ROW(q0.z);
        AG_FMA(r0, __int_as_float(q0.y));
        AG_FMA(r1, __int_as_float(q0.w));
        e += 2;
    }
    if (e < s1) {
        int2 p = __ldg(&g_csrw[e]);
        uint2 r = AG_ROW(p.x);
        AG_FMA(r, __int_as_float(p.y));
    }
#undef AG_ROW
#undef AG_FMA
    acc.x *= di; acc.y *= di; acc.z *= di; acc.w *= di;
    return acc;
}

// ---- agg1: h = Agg(U) + b1  (fp16 in, fp32 out); 128-thread blocks ---------
__global__ void __launch_bounds__(128)
k_agg_bias(const __half* __restrict__ X, float* __restrict__ Y,
           const float* __restrict__ bias, int n) {
    int gw = (blockIdx.x * blockDim.x + threadIdx.x) >> 5;
    int lane = threadIdx.x & 31;
    if (gw >= n) return;
    float di = __ldg(&g_dinv[gw]);
    float4 acc = agg_gather(X, gw, lane, di);
    float4 b = __ldg((const float4*)&bias[lane * 4]);
    acc.x += b.x; acc.y += b.y; acc.z += b.z; acc.w += b.w;
    ((float4*)Y)[(size_t)gw * 32 + lane] = acc;
}

// ---- agg2: [mu|ls] = Agg(V)+bias; out = mu + init*exp(ls) ------------------
__global__ void __launch_bounds__(128)
k_agg_out(const __half* __restrict__ X,
          const float* __restrict__ bmu, const float* __restrict__ bls,
          const float* __restrict__ initd,
          float* __restrict__ out, int n) {
    int gw = (blockIdx.x * blockDim.x + threadIdx.x) >> 5;
    int lane = threadIdx.x & 31;
    if (gw >= n) return;
    float di = __ldg(&g_dinv[gw]);
    float4 v = agg_gather(X, gw, lane, di);
    float4 b = (lane < 16) ? __ldg((const float4*)&bmu[lane * 4])
                           : __ldg((const float4*)&bls[lane * 4 - 64]);
    v.x += b.x; v.y += b.y; v.z += b.z; v.w += b.w;
    float4 p;
    p.x = __shfl_xor_sync(0xFFFFFFFFu, v.x, 16);
    p.y = __shfl_xor_sync(0xFFFFFFFFu, v.y, 16);
    p.z = __shfl_xor_sync(0xFFFFFFFFu, v.z, 16);
    p.w = __shfl_xor_sync(0xFFFFFFFFu, v.w, 16);
    if (lane < 16) {
        float4 ini = __ldg((const float4*)&initd[(size_t)gw * 64 + lane * 4]);
        float4 o;
        o.x = v.x + ini.x * expf(p.x);
        o.y = v.y + ini.y * expf(p.y);
        o.z = v.z + ini.z * expf(p.z);
        o.w = v.w + ini.w * expf(p.w);
        *(float4*)&out[(size_t)gw * 64 + lane * 4] = o;
    }
}

// ================= shared GEMM pieces =======================================
#define KS_B 136
#define SOFF_BH 0
#define SOFF_BL (128 * KS_B * 2)
#define SMEM_MMA (SOFF_BL + 128 * KS_B * 2)

__device__ __forceinline__ void split2(float a, float b, uint32_t& hi, uint32_t& lo) {
    __nv_bfloat16 ah = __float2bfloat16(a), bh = __float2bfloat16(b);
    float ar = a - __bfloat162float(ah);
    float br = b - __bfloat162float(bh);
    __nv_bfloat16 al = __float2bfloat16(ar), bl = __float2bfloat16(br);
    __nv_bfloat162 h; h.x = ah; h.y = bh;
    __nv_bfloat162 l; l.x = al; l.y = bl;
    hi = *(uint32_t*)&h;
    lo = *(uint32_t*)&l;
}

__device__ __forceinline__ uint32_t smem_u32(const void* p) {
    uint32_t a;
    asm("{ .reg .u64 t; cvta.to.shared.u64 t, %1; cvt.u32.u64 %0, t; }" : "=r"(a) : "l"(p));
    return a;
}

__device__ __forceinline__ void mma_bf16(float& c0, float& c1, float& c2, float& c3,
                                         uint32_t a0, uint32_t a1, uint32_t a2, uint32_t a3,
                                         uint32_t b0, uint32_t b1) {
    asm volatile(
        "mma.sync.aligned.m16n8k16.row.col.f32.bf16.bf16.f32 "
        "{%0,%1,%2,%3}, {%4,%5,%6,%7}, {%8,%9}, {%0,%1,%2,%3};"
        : "+f"(c0), "+f"(c1), "+f"(c2), "+f"(c3)
        : "r"(a0), "r"(a1), "r"(a2), "r"(a3), "r"(b0), "r"(b1));
}

__device__ __forceinline__ void ldsm_x2(uint32_t& r0, uint32_t& r1, uint32_t addr) {
    asm volatile("ldmatrix.sync.aligned.m8n8.x2.shared.b16 {%0, %1}, [%2];"
        : "=r"(r0), "=r"(r1) : "r"(addr));
}

// ---- generic split-bf16 3-pass GEMM: fp32 A, fp16 out ----------------------
// Na/Wb support the [Wmu|Wls] concatenation; ei!=null fuses degree count.
__global__ void __launch_bounds__(256)
k_mma_gemm(const float* __restrict__ A,
           const float* __restrict__ Wa, int Na,
           const float* __restrict__ Wb,
           __half* __restrict__ C, int n,
           const int* __restrict__ ei, int e) {
    extern __shared__ char smem[];
    uint16_t* BH = (uint16_t*)(smem + SOFF_BH);
    uint16_t* BL = (uint16_t*)(smem + SOFF_BL);
    int tid = threadIdx.x;
    int wid = tid >> 5, lane = tid & 31;
    int row0 = blockIdx.x * 128;
    int Nb = 128 - Na;

    if (ei) {
        int stride = gridDim.x * blockDim.x;
        for (int i = blockIdx.x * blockDim.x + tid; i < e; i += stride)
            atomicAdd(&g_cnt[__ldg(&ei[e + i])], 1);
    }

    {
        int col = tid >> 1;
        int kbeg = (tid & 1) * 64;
        const float* Wcol = (col < Na) ? (Wa + col) : (Wb + (col - Na));
        int stride = (col < Na) ? Na : Nb;
#pragma unroll 8
        for (int k = kbeg; k < kbeg + 64; k++) {
            float w = __ldg(&Wcol[k * stride]);
            __nv_bfloat16 wh = __float2bfloat16(w);
            float wr = w - __bfloat162float(wh);
            __nv_bfloat16 wl = __float2bfloat16(wr);
            BH[col * KS_B + k] = *(uint16_t*)&wh;
            BL[col * KS_B + k] = *(uint16_t*)&wl;
        }
    }

    int rbase = row0 + wid * 16;
    int r0 = rbase + (lane >> 2);
    int r1 = r0 + 8;
    int r0c = (r0 < n) ? r0 : 0;
    int r1c = (r1 < n) ? r1 : 0;
    const float* A0 = A + (size_t)r0c * 128;
    const float* A1 = A + (size_t)r1c * 128;
    int cc = (lane & 3) * 2;

    uint32_t aH[8][4], aL[8][4];
#pragma unroll
    for (int ks = 0; ks < 8; ks++) {
        int k0 = ks * 16;
        float2 v00 = __ldg((const float2*)&A0[k0 + cc]);
        float2 v10 = __ldg((const float2*)&A1[k0 + cc]);
        float2 v02 = __ldg((const float2*)&A0[k0 + cc + 8]);
        float2 v12 = __ldg((const float2*)&A1[k0 + cc + 8]);
        split2(v00.x, v00.y, aH[ks][0], aL[ks][0]);
        split2(v10.x, v10.y, aH[ks][1], aL[ks][1]);
        split2(v02.x, v02.y, aH[ks][2], aL[ks][2]);
        split2(v12.x, v12.y, aH[ks][3], aL[ks][3]);
    }

    __syncthreads();

    uint32_t bh_base = smem_u32(BH);
    uint32_t bl_base = smem_u32(BL);
    uint32_t lrow = (uint32_t)(lane & 7);
    uint32_t khalf = ((uint32_t)(lane >> 3) & 1) * 8;

    bool w0 = (r0 < n), w1 = (r1 < n);
    __half* C0 = C + (size_t)r0c * 128;
    __half* C1 = C + (size_t)r1c * 128;

#pragma unroll 2
    for (int nb = 0; nb < 16; nb++) {
        int n0 = nb * 8;
        uint32_t off = ((n0 + lrow) * KS_B + khalf) * 2;
        uint32_t adH = bh_base + off;
        uint32_t adL = bl_base + off;
        float c0 = 0.f, c1 = 0.f, c2 = 0.f, c3 = 0.f;
#pragma unroll
        for (int ks = 0; ks < 8; ks++) {
            uint32_t bh0, bh1, bl0, bl1;
            ldsm_x2(bh0, bh1, adH + ks * 32);
            ldsm_x2(bl0, bl1, adL + ks * 32);
            mma_bf16(c0, c1, c2, c3, aH[ks][0], aH[ks][1], aH[ks][2], aH[ks][3], bh0, bh1);
            mma_bf16(c0, c1, c2, c3, aH[ks][0], aH[ks][1], aH[ks][2], aH[ks][3], bl0, bl1);
            mma_bf16(c0, c1, c2, c3, aL[ks][0], aL[ks][1], aL[ks][2], aL[ks][3], bh0, bh1);
        }
        if (w0) *(__half2*)&C0[n0 + cc] = __floats2half2_rn(c0, c1);
        if (w1) *(__half2*)&C1[n0 + cc] = __floats2half2_rn(c2, c3);
    }
}

// ---------------- launch ----------------------------------------------------
extern "C" void kernel_launch(void* const* d_in, const int* in_sizes, int n_in,
                              void* d_out, int out_size) {
    const float* x    = (const float*)d_in[0];
    const int*   ei   = (const int*)d_in[1];
    const float* initd= (const float*)d_in[2];
    const float* W1   = (const float*)d_in[3];
    const float* b1   = (const float*)d_in[4];
    const float* Wmu  = (const float*)d_in[5];
    const float* bmu  = (const float*)d_in[6];
    const float* Wls  = (const float*)d_in[7];
    const float* bls  = (const float*)d_in[8];
    float* out = (float*)d_out;

    int n = in_sizes[0] / FD;
    int e = in_sizes[1] / 2;

    void *pU = nullptr, *pA = nullptr;
    cudaGetSymbolAddress(&pU, g_bufU);
    cudaGetSymbolAddress(&pA, g_bufA);
    __half* bufU = (__half*)pU;
    float*  bufA = (float*)pA;

    cudaFuncSetAttribute(k_mma_gemm, cudaFuncAttributeMaxDynamicSharedMemorySize, SMEM_MMA);

    int agg_grid = (n + 3) / 4;            // 128-thread blocks, 4 warps each
    int gemm_grid = (n + 127) / 128;
    int scan_grid = (n + 255) / 256;
    int fill_grid = ((e + 1) / 2 + 255) / 256;

    // layer-1 GEMM with fused degree count: U = x @ W1 (fp16)
    k_mma_gemm<<<gemm_grid, 256, SMEM_MMA>>>(x, W1, 128, W1, bufU, n, ei, e);

    // CSR: single-pass scan (self-cleaning), then weighted fill (+state reset)
    k_scan_lb<<<scan_grid, 256>>>(n);
    k_fill<<<fill_grid, 256>>>(ei, e);

    // h = Agg(U) + b1 (fp32)
    k_agg_bias<<<agg_grid, 128>>>(bufU, bufA, b1, n);

    // layer 2: V = h @ [Wmu|Wls] (fp16); out = Agg(V)+bias, reparametrized
    k_mma_gemm<<<gemm_grid, 256, SMEM_MMA>>>(bufA, Wmu, 64, Wls, bufU, n, nullptr, 0);
    k_agg_out<<<agg_grid, 128>>>(bufU, bmu, bls, initd, out, n);
}